// round 2
// baseline (speedup 1.0000x reference)
#include <cuda_runtime.h>

#define NN 100000
#define EE 1600000
#define DD 64
#define SCAN_B 1024
#define NB ((NN + SCAN_B - 1) / SCAN_B)   // 98

// ---------------- scratch (static __device__, no allocation) ----------------
__device__ int   g_deg_out[NN];
__device__ int   g_deg_in[NN];
__device__ float g_norm_src[NN];
__device__ float g_norm_dst[NN];
__device__ int   g_row_ptr[NN + 1];
__device__ int   g_fill[NN];
__device__ int   g_col[EE];
__device__ int   g_bsum[NB];
__device__ float g_h[NN * DD];
__device__ float g_bufA[NN * DD];
__device__ float g_bufB[NN * DD];

// ---------------- degree / norm ----------------
__global__ void k_zero() {
    int i = blockIdx.x * blockDim.x + threadIdx.x;
    if (i < NN) {
        g_deg_out[i] = 0;
        g_deg_in[i]  = 0;
        g_fill[i]    = 0;
    }
}

__global__ void k_hist(const int* __restrict__ src, const int* __restrict__ dst) {
    int e = blockIdx.x * blockDim.x + threadIdx.x;
    if (e < EE) {
        atomicAdd(&g_deg_out[src[e]], 1);
        atomicAdd(&g_deg_in[dst[e]], 1);
    }
}

__global__ void k_norm() {
    int i = blockIdx.x * blockDim.x + threadIdx.x;
    if (i < NN) {
        int dout = g_deg_out[i]; if (dout < 1) dout = 1;
        int din  = g_deg_in[i];  if (din  < 1) din  = 1;
        g_norm_src[i] = rsqrtf((float)dout);
        g_norm_dst[i] = rsqrtf((float)din);
    }
}

// ---------------- exclusive scan of deg_in -> row_ptr ----------------
__global__ void k_scan1() {
    __shared__ int sh[SCAN_B];
    int tid = threadIdx.x;
    int i   = blockIdx.x * SCAN_B + tid;
    int v   = (i < NN) ? g_deg_in[i] : 0;
    sh[tid] = v;
    __syncthreads();
    for (int off = 1; off < SCAN_B; off <<= 1) {
        int t = (tid >= off) ? sh[tid - off] : 0;
        __syncthreads();
        sh[tid] += t;
        __syncthreads();
    }
    int incl = sh[tid];
    if (i < NN) g_row_ptr[i] = incl - v;       // exclusive within block
    if (tid == SCAN_B - 1) g_bsum[blockIdx.x] = incl;
}

__global__ void k_scan2() {
    if (threadIdx.x == 0 && blockIdx.x == 0) {
        int run = 0;
        for (int b = 0; b < NB; b++) {
            int t = g_bsum[b];
            g_bsum[b] = run;
            run += t;
        }
        g_row_ptr[NN] = run;   // == EE
    }
}

__global__ void k_scan3() {
    int i = blockIdx.x * blockDim.x + threadIdx.x;
    if (i < NN) g_row_ptr[i] += g_bsum[i >> 10];
}

// ---------------- CSR fill (sorted by dst) ----------------
__global__ void k_fill(const int* __restrict__ src, const int* __restrict__ dst) {
    int e = blockIdx.x * blockDim.x + threadIdx.x;
    if (e < EE) {
        int d   = dst[e];
        int pos = g_row_ptr[d] + atomicAdd(&g_fill[d], 1);
        g_col[pos] = src[e];
    }
}

// ---------------- GEMM: h[n] = (x[n] * norm_src[n]) @ W ----------------
// blockDim 256. Tile: 16 rows. thread (r = tid/16, g = tid%16) computes
// out[r][4g..4g+3]. W (64x64) cached in shared as float4 rows.
#define TILE_R 16
#define XS_STRIDE 72   // pad: bank offset 8 between consecutive rows

__global__ void k_gemm(const float* __restrict__ x, const float* __restrict__ W,
                       float* __restrict__ h) {
    __shared__ float Ws[DD * DD];
    __shared__ float xs[TILE_R * XS_STRIDE];
    int tid = threadIdx.x;

    // load W (4096 floats) cooperatively as float4
    {
        float4* Wd = (float4*)Ws;
        const float4* Wsrc = (const float4*)W;
        #pragma unroll
        for (int i = tid; i < DD * DD / 4; i += 256) Wd[i] = Wsrc[i];
    }
    __syncthreads();

    int r = tid >> 4;    // 0..15
    int g = tid & 15;    // 4-col group

    const int n_tiles = (NN + TILE_R - 1) / TILE_R;
    for (int tile = blockIdx.x; tile < n_tiles; tile += gridDim.x) {
        int base = tile * TILE_R;

        // stage x tile (scaled by norm_src): thread loads one float4
        int rr = tid >> 4;
        int kk = tid & 15;   // float4 index within row
        int n_ld = base + rr;
        float4 xv = make_float4(0.f, 0.f, 0.f, 0.f);
        float ns = 0.f;
        if (n_ld < NN) {
            xv = ((const float4*)x)[n_ld * (DD / 4) + kk];
            ns = g_norm_src[n_ld];
        }
        __syncthreads();   // previous iteration finished reading xs
        xs[rr * XS_STRIDE + kk * 4 + 0] = xv.x * ns;
        xs[rr * XS_STRIDE + kk * 4 + 1] = xv.y * ns;
        xs[rr * XS_STRIDE + kk * 4 + 2] = xv.z * ns;
        xs[rr * XS_STRIDE + kk * 4 + 3] = xv.w * ns;
        __syncthreads();

        int n = base + r;
        if (n < NN) {
            float4 acc = make_float4(0.f, 0.f, 0.f, 0.f);
            const float* xr = &xs[r * XS_STRIDE];
            const float4* W4 = (const float4*)Ws;
            #pragma unroll
            for (int k = 0; k < DD; k++) {
                float xk = xr[k];
                float4 w4 = W4[k * 16 + g];
                acc.x += xk * w4.x;
                acc.y += xk * w4.y;
                acc.z += xk * w4.z;
                acc.w += xk * w4.w;
            }
            ((float4*)h)[n * 16 + g] = acc;
        }
    }
}

// ---------------- aggregation + epilogue ----------------
// one warp per node; each lane owns 2 columns (float2).
// out[n] = relu(segsum(h[src]) * norm_dst[n] + b) + resid[n]
__global__ void k_agg(const float* __restrict__ h, const float* __restrict__ resid,
                      const float* __restrict__ b, float* __restrict__ out) {
    int warp = (blockIdx.x * blockDim.x + threadIdx.x) >> 5;
    int lane = threadIdx.x & 31;
    if (warp >= NN) return;

    int beg = g_row_ptr[warp];
    int end = g_row_ptr[warp + 1];
    const float2* h2 = (const float2*)h;

    float2 acc0 = make_float2(0.f, 0.f);
    float2 acc1 = make_float2(0.f, 0.f);
    int i = beg;
    for (; i + 1 < end; i += 2) {
        int s0 = __ldg(&g_col[i]);
        int s1 = __ldg(&g_col[i + 1]);
        float2 v0 = h2[s0 * 32 + lane];
        float2 v1 = h2[s1 * 32 + lane];
        acc0.x += v0.x; acc0.y += v0.y;
        acc1.x += v1.x; acc1.y += v1.y;
    }
    if (i < end) {
        int s0 = __ldg(&g_col[i]);
        float2 v0 = h2[s0 * 32 + lane];
        acc0.x += v0.x; acc0.y += v0.y;
    }
    float sx = acc0.x + acc1.x;
    float sy = acc0.y + acc1.y;

    float nd = g_norm_dst[warp];
    float2 bb = ((const float2*)b)[lane];
    float2 rr = ((const float2*)resid)[warp * 32 + lane];
    float2 o;
    o.x = fmaxf(sx * nd + bb.x, 0.f) + rr.x;
    o.y = fmaxf(sy * nd + bb.y, 0.f) + rr.y;
    ((float2*)out)[warp * 32 + lane] = o;
}

// ---------------- launch ----------------
extern "C" void kernel_launch(void* const* d_in, const int* in_sizes, int n_in,
                              void* d_out, int out_size) {
    const float* feat = (const float*)d_in[0];
    const int*   src  = (const int*)d_in[1];
    const int*   dst  = (const int*)d_in[2];
    // d_in[3] = etype (unused)
    const float* w1 = (const float*)d_in[4];
    const float* b1 = (const float*)d_in[5];
    const float* w2 = (const float*)d_in[6];
    const float* b2 = (const float*)d_in[7];
    const float* w3 = (const float*)d_in[8];
    const float* b3 = (const float*)d_in[9];
    float* out = (float*)d_out;

    void *ph = nullptr, *pa = nullptr, *pb = nullptr;
    cudaGetSymbolAddress(&ph, g_h);
    cudaGetSymbolAddress(&pa, g_bufA);
    cudaGetSymbolAddress(&pb, g_bufB);
    float* h    = (float*)ph;
    float* bufA = (float*)pa;
    float* bufB = (float*)pb;

    const int gN = (NN + 255) / 256;
    const int gE = (EE + 255) / 256;
    const int gAgg = (NN * 32 + 255) / 256;

    // graph structure (depends only on src/dst, rebuilt each call: deterministic work)
    k_zero<<<gN, 256>>>();
    k_hist<<<gE, 256>>>(src, dst);
    k_norm<<<gN, 256>>>();
    k_scan1<<<NB, SCAN_B>>>();
    k_scan2<<<1, 32>>>();
    k_scan3<<<gN, 256>>>();
    k_fill<<<gE, 256>>>(src, dst);

    // layer 1
    k_gemm<<<2048, 256>>>(feat, w1, h);
    k_agg<<<gAgg, 256>>>(h, feat, b1, bufA);
    // layer 2
    k_gemm<<<2048, 256>>>(bufA, w2, h);
    k_agg<<<gAgg, 256>>>(h, bufA, b2, bufB);
    // layer 3
    k_gemm<<<2048, 256>>>(bufB, w3, h);
    k_agg<<<gAgg, 256>>>(h, bufB, b3, out);
}

// round 4
// speedup vs baseline: 1.3302x; 1.3302x over previous
#include <cuda_runtime.h>

#define NN 100000
#define EE 1600000
#define DD 64
#define SCAN_B 1024
#define NB ((NN + SCAN_B - 1) / SCAN_B)   // 98

// ---------------- scratch (static __device__, no allocation) ----------------
__device__ int   g_deg_out[NN];
__device__ int   g_deg_in[NN];
__device__ float g_norm_src[NN];
__device__ float g_norm_dst[NN];
__device__ int   g_row_ptr[NN + 1];
__device__ int   g_fill[NN];
__device__ int   g_col[EE];
__device__ int   g_bsum[NB];
__device__ float g_h[NN * DD];
__device__ float g_bufA[NN * DD];
__device__ float g_bufB[NN * DD];

// ---------------- degree ----------------
__global__ void k_zero() {
    int i = blockIdx.x * blockDim.x + threadIdx.x;
    if (i < NN) {
        g_deg_out[i] = 0;
        g_deg_in[i]  = 0;
        g_fill[i]    = 0;
    }
}

__global__ void k_hist(const int* __restrict__ src, const int* __restrict__ dst) {
    int e = blockIdx.x * blockDim.x + threadIdx.x;
    if (e < EE) {
        atomicAdd(&g_deg_out[src[e]], 1);
        atomicAdd(&g_deg_in[dst[e]], 1);
    }
}

// ---------------- scan of deg_in -> row_ptr, fused norm computation ----------
__global__ void k_scan1() {
    __shared__ int sh[SCAN_B];
    int tid = threadIdx.x;
    int i   = blockIdx.x * SCAN_B + tid;
    int v   = 0;
    if (i < NN) {
        int din  = g_deg_in[i];
        int dout = g_deg_out[i];
        v = din;
        if (din  < 1) din  = 1;
        if (dout < 1) dout = 1;
        g_norm_src[i] = rsqrtf((float)dout);
        g_norm_dst[i] = rsqrtf((float)din);
    }
    sh[tid] = v;
    __syncthreads();
    for (int off = 1; off < SCAN_B; off <<= 1) {
        int t = (tid >= off) ? sh[tid - off] : 0;
        __syncthreads();
        sh[tid] += t;
        __syncthreads();
    }
    int incl = sh[tid];
    if (i < NN) g_row_ptr[i] = incl - v;       // exclusive within block
    if (tid == SCAN_B - 1) g_bsum[blockIdx.x] = incl;
}

// scan the 98 block sums with one 128-thread block
__global__ void k_scan2() {
    __shared__ int sh[128];
    int tid = threadIdx.x;
    int v = (tid < NB) ? g_bsum[tid] : 0;
    sh[tid] = v;
    __syncthreads();
    for (int off = 1; off < 128; off <<= 1) {
        int t = (tid >= off) ? sh[tid - off] : 0;
        __syncthreads();
        sh[tid] += t;
        __syncthreads();
    }
    if (tid < NB) g_bsum[tid] = sh[tid] - v;    // exclusive
    if (tid == NB - 1) g_row_ptr[NN] = sh[tid]; // == EE
}

__global__ void k_scan3() {
    int i = blockIdx.x * blockDim.x + threadIdx.x;
    if (i < NN) g_row_ptr[i] += g_bsum[i >> 10];
}

// ---------------- CSR fill (grouped by dst) ----------------
__global__ void k_fill(const int* __restrict__ src, const int* __restrict__ dst) {
    int e = blockIdx.x * blockDim.x + threadIdx.x;
    if (e < EE) {
        int d   = dst[e];
        int pos = g_row_ptr[d] + atomicAdd(&g_fill[d], 1);
        g_col[pos] = src[e];
    }
}

// ---------------- GEMM: h[n] = (x[n] * norm_src[n]) @ W ----------------
// 128-row tiles, 256 threads. Thread (rc = tid>>4, g = tid&15) computes
// rows rc*8..rc*8+7, cols 4g..4g+3 (32 accumulators). All shared reads are
// float4: per 4 k's -> 4 W reads + 8 x reads. smem = 16KB + 32KB = 48KB exact.
#define GR 128

__global__ void k_gemm(const float* __restrict__ x, const float* __restrict__ W,
                       float* __restrict__ h) {
    __shared__ float4 Ws4[DD * 16];   // W row-major as float4: Ws4[k*16 + g]
    __shared__ float4 xs4[GR * 16];   // x tile: xs4[row*16 + kq]
    int tid = threadIdx.x;

    {
        const float4* Wsrc = (const float4*)W;
        #pragma unroll
        for (int i = tid; i < DD * 16; i += 256) Ws4[i] = Wsrc[i];
    }

    int rc = tid >> 4;   // 0..15  (8-row chunk)
    int g  = tid & 15;   // 0..15  (4-col group)

    const int n_tiles = (NN + GR - 1) / GR;
    for (int t = blockIdx.x; t < n_tiles; t += gridDim.x) {
        int base = t * GR;

        __syncthreads();   // xs readers of previous tile done (covers W on iter 0)
        #pragma unroll
        for (int i = 0; i < 8; i++) {
            int idx = tid + i * 256;       // 0..2047
            int row = idx >> 4;
            int kq  = idx & 15;
            int n   = base + row;
            float4 v = make_float4(0.f, 0.f, 0.f, 0.f);
            float ns = 0.f;
            if (n < NN) {
                v  = ((const float4*)x)[n * 16 + kq];
                ns = g_norm_src[n];
            }
            v.x *= ns; v.y *= ns; v.z *= ns; v.w *= ns;
            xs4[row * 16 + kq] = v;
        }
        __syncthreads();

        float4 acc[8];
        #pragma unroll
        for (int j = 0; j < 8; j++) acc[j] = make_float4(0.f, 0.f, 0.f, 0.f);

        #pragma unroll
        for (int kq = 0; kq < 16; kq++) {
            float4 w0 = Ws4[(4 * kq + 0) * 16 + g];
            float4 w1 = Ws4[(4 * kq + 1) * 16 + g];
            float4 w2 = Ws4[(4 * kq + 2) * 16 + g];
            float4 w3 = Ws4[(4 * kq + 3) * 16 + g];
            #pragma unroll
            for (int j = 0; j < 8; j++) {
                float4 xv = xs4[(rc * 8 + j) * 16 + kq];
                acc[j].x += xv.x * w0.x; acc[j].y += xv.x * w0.y;
                acc[j].z += xv.x * w0.z; acc[j].w += xv.x * w0.w;
                acc[j].x += xv.y * w1.x; acc[j].y += xv.y * w1.y;
                acc[j].z += xv.y * w1.z; acc[j].w += xv.y * w1.w;
                acc[j].x += xv.z * w2.x; acc[j].y += xv.z * w2.y;
                acc[j].z += xv.z * w2.z; acc[j].w += xv.z * w2.w;
                acc[j].x += xv.w * w3.x; acc[j].y += xv.w * w3.y;
                acc[j].z += xv.w * w3.z; acc[j].w += xv.w * w3.w;
            }
        }

        #pragma unroll
        for (int j = 0; j < 8; j++) {
            int n = base + rc * 8 + j;
            if (n < NN) ((float4*)h)[n * 16 + g] = acc[j];
        }
    }
}

// ---------------- aggregation + epilogue ----------------
// one warp per node; each lane owns 2 columns (float2); 4 edges in flight.
// out[n] = relu(segsum(h[src]) * norm_dst[n] + b) + resid[n]
__global__ void k_agg(const float* __restrict__ h, const float* __restrict__ resid,
                      const float* __restrict__ b, float* __restrict__ out) {
    int warp = (blockIdx.x * blockDim.x + threadIdx.x) >> 5;
    int lane = threadIdx.x & 31;
    if (warp >= NN) return;

    int beg = g_row_ptr[warp];
    int end = g_row_ptr[warp + 1];
    const float2* h2 = (const float2*)h;

    float2 a0 = make_float2(0.f, 0.f);
    float2 a1 = make_float2(0.f, 0.f);
    float2 a2 = make_float2(0.f, 0.f);
    float2 a3 = make_float2(0.f, 0.f);
    int i = beg;
    for (; i + 3 < end; i += 4) {
        int s0 = __ldg(&g_col[i]);
        int s1 = __ldg(&g_col[i + 1]);
        int s2 = __ldg(&g_col[i + 2]);
        int s3 = __ldg(&g_col[i + 3]);
        float2 v0 = h2[s0 * 32 + lane];
        float2 v1 = h2[s1 * 32 + lane];
        float2 v2 = h2[s2 * 32 + lane];
        float2 v3 = h2[s3 * 32 + lane];
        a0.x += v0.x; a0.y += v0.y;
        a1.x += v1.x; a1.y += v1.y;
        a2.x += v2.x; a2.y += v2.y;
        a3.x += v3.x; a3.y += v3.y;
    }
    for (; i < end; i++) {
        int s0 = __ldg(&g_col[i]);
        float2 v0 = h2[s0 * 32 + lane];
        a0.x += v0.x; a0.y += v0.y;
    }
    float sx = (a0.x + a1.x) + (a2.x + a3.x);
    float sy = (a0.y + a1.y) + (a2.y + a3.y);

    float nd = g_norm_dst[warp];
    float2 bb = ((const float2*)b)[lane];
    float2 rr = ((const float2*)resid)[warp * 32 + lane];
    float2 o;
    o.x = fmaxf(sx * nd + bb.x, 0.f) + rr.x;
    o.y = fmaxf(sy * nd + bb.y, 0.f) + rr.y;
    ((float2*)out)[warp * 32 + lane] = o;
}

// ---------------- launch ----------------
extern "C" void kernel_launch(void* const* d_in, const int* in_sizes, int n_in,
                              void* d_out, int out_size) {
    const float* feat = (const float*)d_in[0];
    const int*   src  = (const int*)d_in[1];
    const int*   dst  = (const int*)d_in[2];
    // d_in[3] = etype (unused)
    const float* w1 = (const float*)d_in[4];
    const float* b1 = (const float*)d_in[5];
    const float* w2 = (const float*)d_in[6];
    const float* b2 = (const float*)d_in[7];
    const float* w3 = (const float*)d_in[8];
    const float* b3 = (const float*)d_in[9];
    float* out = (float*)d_out;

    void *ph = nullptr, *pa = nullptr, *pb = nullptr;
    cudaGetSymbolAddress(&ph, g_h);
    cudaGetSymbolAddress(&pa, g_bufA);
    cudaGetSymbolAddress(&pb, g_bufB);
    float* h    = (float*)ph;
    float* bufA = (float*)pa;
    float* bufB = (float*)pb;

    const int gN = (NN + 255) / 256;
    const int gE = (EE + 255) / 256;
    const int gAgg = (NN * 32 + 255) / 256;
    const int gGemm = (NN + GR - 1) / GR;   // 782 tiles, one per block

    // graph structure (depends only on src/dst, rebuilt each call: deterministic)
    k_zero<<<gN, 256>>>();
    k_hist<<<gE, 256>>>(src, dst);
    k_scan1<<<NB, SCAN_B>>>();
    k_scan2<<<1, 128>>>();
    k_scan3<<<gN, 256>>>();
    k_fill<<<gE, 256>>>(src, dst);

    // layer 1
    k_gemm<<<gGemm, 256>>>(feat, w1, h);
    k_agg<<<gAgg, 256>>>(h, feat, b1, bufA);
    // layer 2
    k_gemm<<<gGemm, 256>>>(bufA, w2, h);
    k_agg<<<gAgg, 256>>>(h, bufA, b2, bufB);
    // layer 3
    k_gemm<<<gGemm, 256>>>(bufB, w3, h);
    k_agg<<<gAgg, 256>>>(h, bufB, b3, out);
}

// round 5
// speedup vs baseline: 1.3772x; 1.0354x over previous
#include <cuda_runtime.h>
#include <cuda_fp16.h>

#define NN 100000
#define EE 1600000
#define DD 64
#define SCAN_B 1024
#define NB ((NN + SCAN_B - 1) / SCAN_B)   // 98

// ---------------- scratch (static __device__, no allocation) ----------------
__device__ int    g_deg_out[NN];
__device__ int    g_deg_in[NN];
__device__ float  g_norm_src[NN];
__device__ float  g_norm_dst[NN];
__device__ int    g_row_ptr[NN + 1];
__device__ int    g_fill[NN];
__device__ int    g_col[EE];
__device__ int    g_bsum[NB];
__device__ __half g_h[NN * DD];           // fp16 intermediate (halves gather bytes)
__device__ float  g_bufA[NN * DD];
__device__ float  g_bufB[NN * DD];

// ---------------- degree ----------------
__global__ void k_zero() {
    int i = blockIdx.x * blockDim.x + threadIdx.x;
    if (i < NN) {
        g_deg_out[i] = 0;
        g_deg_in[i]  = 0;
        g_fill[i]    = 0;
    }
}

__global__ void k_hist(const int* __restrict__ src, const int* __restrict__ dst) {
    int e = blockIdx.x * blockDim.x + threadIdx.x;
    if (e < EE) {
        atomicAdd(&g_deg_out[src[e]], 1);
        atomicAdd(&g_deg_in[dst[e]], 1);
    }
}

// ---------------- scan of deg_in -> row_ptr, fused norm computation ----------
__global__ void k_scan1() {
    __shared__ int sh[SCAN_B];
    int tid = threadIdx.x;
    int i   = blockIdx.x * SCAN_B + tid;
    int v   = 0;
    if (i < NN) {
        int din  = g_deg_in[i];
        int dout = g_deg_out[i];
        v = din;
        if (din  < 1) din  = 1;
        if (dout < 1) dout = 1;
        g_norm_src[i] = rsqrtf((float)dout);
        g_norm_dst[i] = rsqrtf((float)din);
    }
    sh[tid] = v;
    __syncthreads();
    for (int off = 1; off < SCAN_B; off <<= 1) {
        int t = (tid >= off) ? sh[tid - off] : 0;
        __syncthreads();
        sh[tid] += t;
        __syncthreads();
    }
    int incl = sh[tid];
    if (i < NN) g_row_ptr[i] = incl - v;       // exclusive within block
    if (tid == SCAN_B - 1) g_bsum[blockIdx.x] = incl;
}

// scan the 98 block sums with one 128-thread block
__global__ void k_scan2() {
    __shared__ int sh[128];
    int tid = threadIdx.x;
    int v = (tid < NB) ? g_bsum[tid] : 0;
    sh[tid] = v;
    __syncthreads();
    for (int off = 1; off < 128; off <<= 1) {
        int t = (tid >= off) ? sh[tid - off] : 0;
        __syncthreads();
        sh[tid] += t;
        __syncthreads();
    }
    if (tid < NB) g_bsum[tid] = sh[tid] - v;    // exclusive
    if (tid == NB - 1) g_row_ptr[NN] = sh[tid]; // == EE
}

__global__ void k_scan3() {
    int i = blockIdx.x * blockDim.x + threadIdx.x;
    if (i < NN) g_row_ptr[i] += g_bsum[i >> 10];
}

// ---------------- CSR fill (grouped by dst) ----------------
__global__ void k_fill(const int* __restrict__ src, const int* __restrict__ dst) {
    int e = blockIdx.x * blockDim.x + threadIdx.x;
    if (e < EE) {
        int d   = dst[e];
        int pos = g_row_ptr[d] + atomicAdd(&g_fill[d], 1);
        g_col[pos] = src[e];
    }
}

// ---------------- GEMM: h[n] = fp16( (x[n] * norm_src[n]) @ W ) --------------
// 128-row tiles, 256 threads. Thread (rc = tid>>4, g = tid&15) computes
// rows rc*8..rc*8+7, cols 4g..4g+3 (32 accumulators). All shared reads are
// float4. smem = 16KB + 32KB = 48KB exact.
#define GR 128

__global__ void k_gemm(const float* __restrict__ x, const float* __restrict__ W,
                       __half* __restrict__ h) {
    __shared__ float4 Ws4[DD * 16];   // W row-major as float4: Ws4[k*16 + g]
    __shared__ float4 xs4[GR * 16];   // x tile: xs4[row*16 + kq]
    int tid = threadIdx.x;

    {
        const float4* Wsrc = (const float4*)W;
        #pragma unroll
        for (int i = tid; i < DD * 16; i += 256) Ws4[i] = Wsrc[i];
    }

    int rc = tid >> 4;   // 0..15  (8-row chunk)
    int g  = tid & 15;   // 0..15  (4-col group)

    const int n_tiles = (NN + GR - 1) / GR;
    for (int t = blockIdx.x; t < n_tiles; t += gridDim.x) {
        int base = t * GR;

        __syncthreads();   // xs readers of previous tile done (covers W on iter 0)
        #pragma unroll
        for (int i = 0; i < 8; i++) {
            int idx = tid + i * 256;       // 0..2047
            int row = idx >> 4;
            int kq  = idx & 15;
            int n   = base + row;
            float4 v = make_float4(0.f, 0.f, 0.f, 0.f);
            float ns = 0.f;
            if (n < NN) {
                v  = ((const float4*)x)[n * 16 + kq];
                ns = g_norm_src[n];
            }
            v.x *= ns; v.y *= ns; v.z *= ns; v.w *= ns;
            xs4[row * 16 + kq] = v;
        }
        __syncthreads();

        float4 acc[8];
        #pragma unroll
        for (int j = 0; j < 8; j++) acc[j] = make_float4(0.f, 0.f, 0.f, 0.f);

        #pragma unroll
        for (int kq = 0; kq < 16; kq++) {
            float4 w0 = Ws4[(4 * kq + 0) * 16 + g];
            float4 w1 = Ws4[(4 * kq + 1) * 16 + g];
            float4 w2 = Ws4[(4 * kq + 2) * 16 + g];
            float4 w3 = Ws4[(4 * kq + 3) * 16 + g];
            #pragma unroll
            for (int j = 0; j < 8; j++) {
                float4 xv = xs4[(rc * 8 + j) * 16 + kq];
                acc[j].x += xv.x * w0.x; acc[j].y += xv.x * w0.y;
                acc[j].z += xv.x * w0.z; acc[j].w += xv.x * w0.w;
                acc[j].x += xv.y * w1.x; acc[j].y += xv.y * w1.y;
                acc[j].z += xv.y * w1.z; acc[j].w += xv.y * w1.w;
                acc[j].x += xv.z * w2.x; acc[j].y += xv.z * w2.y;
                acc[j].z += xv.z * w2.z; acc[j].w += xv.z * w2.w;
                acc[j].x += xv.w * w3.x; acc[j].y += xv.w * w3.y;
                acc[j].z += xv.w * w3.z; acc[j].w += xv.w * w3.w;
            }
        }

        #pragma unroll
        for (int j = 0; j < 8; j++) {
            int n = base + rc * 8 + j;
            if (n < NN) {
                __half2 lo = __floats2half2_rn(acc[j].x, acc[j].y);
                __half2 hi = __floats2half2_rn(acc[j].z, acc[j].w);
                uint2 pk;
                pk.x = *(unsigned int*)&lo;
                pk.y = *(unsigned int*)&hi;
                ((uint2*)h)[n * 16 + g] = pk;   // 8B store: cols 4g..4g+3
            }
        }
    }
}

// ---------------- aggregation + epilogue ----------------
// one warp per node; lane owns 2 columns (__half2 = 4B, warp row = 128B line);
// 4 edges in flight. out[n] = relu(segsum(h[src])*norm_dst[n] + b) + resid[n]
__global__ void k_agg(const __half* __restrict__ h, const float* __restrict__ resid,
                      const float* __restrict__ b, float* __restrict__ out) {
    int warp = (blockIdx.x * blockDim.x + threadIdx.x) >> 5;
    int lane = threadIdx.x & 31;
    if (warp >= NN) return;

    int beg = g_row_ptr[warp];
    int end = g_row_ptr[warp + 1];
    const __half2* h2 = (const __half2*)h;

    float2 a0 = make_float2(0.f, 0.f);
    float2 a1 = make_float2(0.f, 0.f);
    float2 a2 = make_float2(0.f, 0.f);
    float2 a3 = make_float2(0.f, 0.f);
    int i = beg;
    for (; i + 3 < end; i += 4) {
        int s0 = __ldg(&g_col[i]);
        int s1 = __ldg(&g_col[i + 1]);
        int s2 = __ldg(&g_col[i + 2]);
        int s3 = __ldg(&g_col[i + 3]);
        float2 v0 = __half22float2(h2[s0 * 32 + lane]);
        float2 v1 = __half22float2(h2[s1 * 32 + lane]);
        float2 v2 = __half22float2(h2[s2 * 32 + lane]);
        float2 v3 = __half22float2(h2[s3 * 32 + lane]);
        a0.x += v0.x; a0.y += v0.y;
        a1.x += v1.x; a1.y += v1.y;
        a2.x += v2.x; a2.y += v2.y;
        a3.x += v3.x; a3.y += v3.y;
    }
    for (; i < end; i++) {
        int s0 = __ldg(&g_col[i]);
        float2 v0 = __half22float2(h2[s0 * 32 + lane]);
        a0.x += v0.x; a0.y += v0.y;
    }
    float sx = (a0.x + a1.x) + (a2.x + a3.x);
    float sy = (a0.y + a1.y) + (a2.y + a3.y);

    float nd = g_norm_dst[warp];
    float2 bb = ((const float2*)b)[lane];
    float2 rr = ((const float2*)resid)[warp * 32 + lane];
    float2 o;
    o.x = fmaxf(sx * nd + bb.x, 0.f) + rr.x;
    o.y = fmaxf(sy * nd + bb.y, 0.f) + rr.y;
    ((float2*)out)[warp * 32 + lane] = o;
}

// ---------------- launch ----------------
extern "C" void kernel_launch(void* const* d_in, const int* in_sizes, int n_in,
                              void* d_out, int out_size) {
    const float* feat = (const float*)d_in[0];
    const int*   src  = (const int*)d_in[1];
    const int*   dst  = (const int*)d_in[2];
    // d_in[3] = etype (unused)
    const float* w1 = (const float*)d_in[4];
    const float* b1 = (const float*)d_in[5];
    const float* w2 = (const float*)d_in[6];
    const float* b2 = (const float*)d_in[7];
    const float* w3 = (const float*)d_in[8];
    const float* b3 = (const float*)d_in[9];
    float* out = (float*)d_out;

    void *ph = nullptr, *pa = nullptr, *pb = nullptr;
    cudaGetSymbolAddress(&ph, g_h);
    cudaGetSymbolAddress(&pa, g_bufA);
    cudaGetSymbolAddress(&pb, g_bufB);
    __half* h   = (__half*)ph;
    float* bufA = (float*)pa;
    float* bufB = (float*)pb;

    const int gN = (NN + 255) / 256;
    const int gE = (EE + 255) / 256;
    const int gAgg = (NN * 32 + 255) / 256;
    const int gGemm = (NN + GR - 1) / GR;

    // graph structure (depends only on src/dst, rebuilt each call: deterministic)
    k_zero<<<gN, 256>>>();
    k_hist<<<gE, 256>>>(src, dst);
    k_scan1<<<NB, SCAN_B>>>();
    k_scan2<<<1, 128>>>();
    k_scan3<<<gN, 256>>>();
    k_fill<<<gE, 256>>>(src, dst);

    // layer 1
    k_gemm<<<gGemm, 256>>>(feat, w1, h);
    k_agg<<<gAgg, 256>>>(h, feat, b1, bufA);
    // layer 2
    k_gemm<<<gGemm, 256>>>(bufA, w2, h);
    k_agg<<<gAgg, 256>>>(h, bufA, b2, bufB);
    // layer 3
    k_gemm<<<gGemm, 256>>>(bufB, w3, h);
    k_agg<<<gAgg, 256>>>(h, bufB, b3, out);
}